// round 1
// baseline (speedup 1.0000x reference)
#include <cuda_runtime.h>
#include <math.h>

#define BDIM 16384
#define HDIM 512
#define NTAU 5
#define EPSV 1e-5f

// ---------------- scratch (static __device__: allocation-guard safe) --------
__device__ float g_bufT[(size_t)BDIM * 3 * HDIM];   // 96 MB
__device__ float g_bufS[(size_t)BDIM * 3 * HDIM];   // 96 MB
__device__ float g_snext[(size_t)BDIM * HDIM];      // 32 MB
__device__ float g_tnext[(size_t)BDIM * HDIM];      // 32 MB
__device__ float g_tfus[(size_t)BDIM * HDIM];       // 32 MB

// ---------------- fp32 SGEMM, 128x128 block tile, BK=8, 8x8 per thread -----
__global__ void __launch_bounds__(256, 2) sgemm_bias(
    const float* __restrict__ A, const float* __restrict__ W,
    const float* __restrict__ bias, float* __restrict__ C,
    int M, int N, int K)
{
    constexpr int BM = 128, BN = 128, BK = 8, TM = 8, TN = 8;
    __shared__ float As[BK][BM];
    __shared__ float Bs[BK][BN];

    const int tid  = threadIdx.x;
    const int tx   = tid & 15;        // 16 thread cols
    const int ty   = tid >> 4;        // 16 thread rows
    const int arow = tid >> 1;        // A tile: 128 rows x 8 cols
    const int acol = (tid & 1) << 2;
    const int wrow = tid >> 5;        // W tile: 8 rows x 128 cols
    const int wcol = (tid & 31) << 2;

    const float* Ab = A + (size_t)(blockIdx.y * BM) * K;
    const float* Wb = W + blockIdx.x * BN;

    float acc[TM][TN] = {};

    for (int k0 = 0; k0 < K; k0 += BK) {
        float4 a4 = *reinterpret_cast<const float4*>(Ab + (size_t)arow * K + k0 + acol);
        As[acol + 0][arow] = a4.x;
        As[acol + 1][arow] = a4.y;
        As[acol + 2][arow] = a4.z;
        As[acol + 3][arow] = a4.w;
        *reinterpret_cast<float4*>(&Bs[wrow][wcol]) =
            *reinterpret_cast<const float4*>(Wb + (size_t)(k0 + wrow) * N + wcol);
        __syncthreads();

        #pragma unroll
        for (int k = 0; k < BK; ++k) {
            float ar[TM], br[TN];
            #pragma unroll
            for (int i = 0; i < TM; ++i) ar[i] = As[k][ty * TM + i];
            #pragma unroll
            for (int j = 0; j < TN; ++j) br[j] = Bs[k][tx * TN + j];
            #pragma unroll
            for (int i = 0; i < TM; ++i)
                #pragma unroll
                for (int j = 0; j < TN; ++j)
                    acc[i][j] = fmaf(ar[i], br[j], acc[i][j]);
        }
        __syncthreads();
    }

    const int crow0 = blockIdx.y * BM + ty * TM;
    const int ccol0 = blockIdx.x * BN + tx * TN;
    #pragma unroll
    for (int i = 0; i < TM; ++i) {
        #pragma unroll
        for (int j = 0; j < TN; j += 4) {
            float4 o;
            o.x = acc[i][j + 0] + bias[ccol0 + j + 0];
            o.y = acc[i][j + 1] + bias[ccol0 + j + 1];
            o.z = acc[i][j + 2] + bias[ccol0 + j + 2];
            o.w = acc[i][j + 3] + bias[ccol0 + j + 3];
            *reinterpret_cast<float4*>(C + (size_t)(crow0 + i) * N + ccol0 + j) = o;
        }
    }
}

// ---------------- row LayerNorm (N = 512 or 1536), 256 threads/row ---------
__global__ void __launch_bounds__(256) ln_kernel(
    const float* __restrict__ X, const float* __restrict__ gamma,
    const float* __restrict__ beta, float* __restrict__ Y, int N)
{
    const int b = blockIdx.x;
    const float* x = X + (size_t)b * N;
    float* y       = Y + (size_t)b * N;
    const int cnt = N >> 8;                  // 2 or 6
    float v[6];
    float s = 0.f, ss = 0.f;
    for (int i = 0; i < cnt; ++i) {
        float t = x[threadIdx.x + (i << 8)];
        v[i] = t;
        s += t;
        ss = fmaf(t, t, ss);
    }
    __shared__ float sh[2][8];
    const int lane = threadIdx.x & 31, w = threadIdx.x >> 5;
    #pragma unroll
    for (int o = 16; o > 0; o >>= 1) {
        s  += __shfl_down_sync(0xffffffffu, s, o);
        ss += __shfl_down_sync(0xffffffffu, ss, o);
    }
    if (lane == 0) { sh[0][w] = s; sh[1][w] = ss; }
    __syncthreads();
    if (w == 0) {
        s  = (lane < 8) ? sh[0][lane] : 0.f;
        ss = (lane < 8) ? sh[1][lane] : 0.f;
        #pragma unroll
        for (int o = 4; o > 0; o >>= 1) {
            s  += __shfl_down_sync(0xffffffffu, s, o);
            ss += __shfl_down_sync(0xffffffffu, ss, o);
        }
        if (lane == 0) { sh[0][0] = s; sh[1][0] = ss; }
    }
    __syncthreads();
    const float invN = 1.0f / (float)N;
    const float mu   = sh[0][0] * invN;
    const float var  = sh[1][0] * invN - mu * mu;
    const float r    = rsqrtf(var + EPSV);
    for (int i = 0; i < cnt; ++i) {
        int c = threadIdx.x + (i << 8);
        y[c] = (v[i] - mu) * r * gamma[c] + beta[c];
    }
}

// ---------------- attention over tau + trend + fusion gate -----------------
__global__ void __launch_bounds__(128) attn_fusion(
    const float* __restrict__ T_t,   const float* __restrict__ t_att,
    const float* __restrict__ s_att, const float* __restrict__ s_next,
    const float* __restrict__ t_next, float* __restrict__ T_fusion)
{
    const int b = blockIdx.x;
    const int tid = threadIdx.x;
    const size_t off = (size_t)b * HDIM;

    float sn[4];
    #pragma unroll
    for (int i = 0; i < 4; ++i) sn[i] = s_next[off + tid + i * 128];

    float dot[NTAU];
    #pragma unroll
    for (int t = 0; t < NTAU; ++t) {
        const float* sa = s_att + ((size_t)t * BDIM + b) * HDIM;
        float d = 0.f;
        #pragma unroll
        for (int i = 0; i < 4; ++i) d = fmaf(sa[tid + i * 128], sn[i], d);
        dot[t] = d;
    }

    __shared__ float sh[NTAU][4];
    const int lane = tid & 31, w = tid >> 5;
    #pragma unroll
    for (int t = 0; t < NTAU; ++t) {
        float d = dot[t];
        #pragma unroll
        for (int o = 16; o > 0; o >>= 1) d += __shfl_down_sync(0xffffffffu, d, o);
        if (lane == 0) sh[t][w] = d;
    }
    __syncthreads();

    const float scale = rsqrtf((float)HDIM);
    float wt[NTAU], mx = -1e30f;
    #pragma unroll
    for (int t = 0; t < NTAU; ++t) {
        float v = (sh[t][0] + sh[t][1] + sh[t][2] + sh[t][3]) * scale;
        wt[t] = v;
        mx = fmaxf(mx, v);
    }
    float sum = 0.f;
    #pragma unroll
    for (int t = 0; t < NTAU; ++t) { wt[t] = expf(wt[t] - mx); sum += wt[t]; }
    const float inv = 1.0f / sum;

    #pragma unroll
    for (int i = 0; i < 4; ++i) {
        const int col = tid + i * 128;
        float trend = 0.f;
        #pragma unroll
        for (int t = 0; t < NTAU; ++t)
            trend = fmaf(wt[t], t_att[((size_t)t * BDIM + b) * HDIM + col], trend);
        trend *= inv;
        const float g = 1.0f / (1.0f + expf(-t_next[off + col]));
        T_fusion[off + col] = T_t[off + col] * g + (1.0f - g) * trend;
    }
}

// ---------------- final split / gating / residual --------------------------
__global__ void __launch_bounds__(256) final_gate(
    const float* __restrict__ Tcat, const float* __restrict__ Scat,
    const float* __restrict__ S_t,  float* __restrict__ out)
{
    const size_t i = (size_t)blockIdx.x * 256 + threadIdx.x;   // over B*H
    const int b = (int)(i >> 9);       // /512
    const int j = (int)(i & 511);
    const float* tr = Tcat + (size_t)b * 3 * HDIM;
    const float* sr = Scat + (size_t)b * 3 * HDIM;
    const float tg = 1.0f / (1.0f + expf(-tr[j]));
    const float sg = 1.0f / (1.0f + expf(-sr[j]));
    const float T_new = tg * tr[HDIM + j] + (1.0f - tg) * sr[HDIM + j];
    const float S_new = sg * sr[2 * HDIM + j] + (1.0f - sg) * tr[2 * HDIM + j] + S_t[i];
    out[i] = T_new;
    out[(size_t)BDIM * HDIM + i] = S_new;
}

// ---------------- launch ----------------------------------------------------
extern "C" void kernel_launch(void* const* d_in, const int* in_sizes, int n_in,
                              void* d_out, int out_size)
{
    const float* T_t   = (const float*)d_in[0];
    const float* S_t   = (const float*)d_in[1];
    const float* t_att = (const float*)d_in[2];
    const float* s_att = (const float*)d_in[3];
    const float* W_tn  = (const float*)d_in[4];
    const float* b_tn  = (const float*)d_in[5];
    const float* g_tn  = (const float*)d_in[6];
    const float* be_tn = (const float*)d_in[7];
    const float* W_sn  = (const float*)d_in[8];
    const float* b_sn  = (const float*)d_in[9];
    const float* g_sn  = (const float*)d_in[10];
    const float* be_sn = (const float*)d_in[11];
    const float* W_t   = (const float*)d_in[12];
    const float* b_t   = (const float*)d_in[13];
    const float* g_t   = (const float*)d_in[14];
    const float* be_t  = (const float*)d_in[15];
    const float* W_s   = (const float*)d_in[16];
    const float* b_s   = (const float*)d_in[17];
    const float* g_s   = (const float*)d_in[18];
    const float* be_s  = (const float*)d_in[19];
    float* out = (float*)d_out;

    float *bufT, *bufS, *snext, *tnext, *tfus;
    cudaGetSymbolAddress((void**)&bufT,  g_bufT);
    cudaGetSymbolAddress((void**)&bufS,  g_bufS);
    cudaGetSymbolAddress((void**)&snext, g_snext);
    cudaGetSymbolAddress((void**)&tnext, g_tnext);
    cudaGetSymbolAddress((void**)&tfus,  g_tfus);

    const dim3 gH(HDIM / 128, BDIM / 128);        // 4 x 128
    const dim3 g3H(3 * HDIM / 128, BDIM / 128);   // 12 x 128

    // s_next = LN(S_t @ W_sn + b_sn)
    sgemm_bias<<<gH, 256>>>(S_t, W_sn, b_sn, bufS, BDIM, HDIM, HDIM);
    ln_kernel<<<BDIM, 256>>>(bufS, g_sn, be_sn, snext, HDIM);
    // t_next = LN(T_t @ W_tn + b_tn)
    sgemm_bias<<<gH, 256>>>(T_t, W_tn, b_tn, bufT, BDIM, HDIM, HDIM);
    ln_kernel<<<BDIM, 256>>>(bufT, g_tn, be_tn, tnext, HDIM);
    // attention + fusion gate
    attn_fusion<<<BDIM, 128>>>(T_t, t_att, s_att, snext, tnext, tfus);
    // T_concat = LN(T_fusion @ W_t + b_t)   (LN in place)
    sgemm_bias<<<g3H, 256>>>(tfus, W_t, b_t, bufT, BDIM, 3 * HDIM, HDIM);
    ln_kernel<<<BDIM, 256>>>(bufT, g_t, be_t, bufT, 3 * HDIM);
    // S_concat = LN(S_t @ W_s + b_s)        (LN in place)
    sgemm_bias<<<g3H, 256>>>(S_t, W_s, b_s, bufS, BDIM, 3 * HDIM, HDIM);
    ln_kernel<<<BDIM, 256>>>(bufS, g_s, be_s, bufS, 3 * HDIM);
    // outputs
    final_gate<<<(BDIM * HDIM) / 256, 256>>>(bufT, bufS, S_t, out);
}

// round 3
// speedup vs baseline: 2.1040x; 2.1040x over previous
#include <cuda_runtime.h>
#include <math.h>
#include <stdint.h>

#define BDIM 16384
#define HDIM 512
#define NTAU 5
#define EPSV 1e-5f

// ---------------- scratch (static __device__: allocation-guard safe) --------
__device__ float g_bufT[(size_t)BDIM * 3 * HDIM];   // 96 MB
__device__ float g_bufS[(size_t)BDIM * 3 * HDIM];   // 96 MB
__device__ float g_snext[(size_t)BDIM * HDIM];
__device__ float g_tnext[(size_t)BDIM * HDIM];
__device__ float g_tfus[(size_t)BDIM * HDIM];       // tf32-rounded
__device__ float g_Tr[(size_t)BDIM * HDIM];         // tf32-rounded T_t
__device__ float g_Sr[(size_t)BDIM * HDIM];         // tf32-rounded S_t
__device__ float g_Wtn_t[(size_t)HDIM * HDIM];      // transposed+rounded weights
__device__ float g_Wsn_t[(size_t)HDIM * HDIM];
__device__ float g_Wt_t[(size_t)3 * HDIM * HDIM];
__device__ float g_Ws_t[(size_t)3 * HDIM * HDIM];

// ---------------- helpers ----------------------------------------------------
__device__ __forceinline__ uint32_t smem_u32(const void* p) {
    uint32_t a;
    asm("{ .reg .u64 t; cvta.to.shared.u64 t, %1; cvt.u32.u64 %0, t; }" : "=r"(a) : "l"(p));
    return a;
}
__device__ __forceinline__ float rna_tf32(float x) {
    uint32_t r;
    asm("cvt.rna.tf32.f32 %0, %1;" : "=r"(r) : "f"(x));
    return __uint_as_float(r);
}
#define CP16(s, g) asm volatile("cp.async.cg.shared.global [%0], [%1], 16;" :: "r"(s), "l"(g))
#define CP_COMMIT() asm volatile("cp.async.commit_group;" ::: "memory")

// ---------------- weight transpose + RNA-tf32 round -------------------------
__global__ void transpose_rna(const float* __restrict__ W, float* __restrict__ Wt,
                              int K, int N)
{
    __shared__ float tile[32][33];
    const int x = blockIdx.x * 32 + threadIdx.x;   // n
    const int y = blockIdx.y * 32 + threadIdx.y;   // k
    tile[threadIdx.y][threadIdx.x] = W[(size_t)y * N + x];
    __syncthreads();
    const int xo = blockIdx.y * 32 + threadIdx.x;  // k
    const int yo = blockIdx.x * 32 + threadIdx.y;  // n
    Wt[(size_t)yo * K + xo] = rna_tf32(tile[threadIdx.x][threadIdx.y]);
}

// ---------------- RNA-tf32 rounding copy -------------------------------------
__global__ void __launch_bounds__(256) rna_copy(const float* __restrict__ in,
                                                float* __restrict__ out)
{
    const size_t i = ((size_t)blockIdx.x * 256 + threadIdx.x) * 4;
    float4 v = *reinterpret_cast<const float4*>(in + i);
    v.x = rna_tf32(v.x); v.y = rna_tf32(v.y);
    v.z = rna_tf32(v.z); v.w = rna_tf32(v.w);
    *reinterpret_cast<float4*>(out + i) = v;
}

// ---------------- tf32 mma.sync GEMM: C[M,N] = A[M,K] * Bt[N,K]^T + bias ----
// 128x128 CTA tile, BK=16, 3-stage cp.async, warp tile 64x32 (4x4 m16n8k8).
__global__ void __launch_bounds__(256, 2) gemm_tf32(
    const float* __restrict__ A, const float* __restrict__ Bt,
    const float* __restrict__ bias, float* __restrict__ C, int N)
{
    constexpr int K = 512, BK = 16, NT = K / BK;   // 32 k-iters
    constexpr int LDP = 20;                        // padded row stride (floats)
    constexpr int STGF = 128 * LDP;                // floats per operand tile (2560)
    constexpr int STAGEF = 2 * STGF;               // floats per stage (A+B)
    extern __shared__ float smf[];

    const int tid  = threadIdx.x;
    const int wid  = tid >> 5;
    const int lane = tid & 31;
    const int wm   = wid & 1;      // 2 m-groups of 64
    const int wn   = wid >> 1;     // 4 n-groups of 32
    const int m0 = blockIdx.y * 128;
    const int n0 = blockIdx.x * 128;

    // cp.async: 2 threads per row, each thread 2x16B chunks per operand
    const int r   = tid >> 1;          // 0..127
    const int ch  = tid & 1;           // chunk 0/1 (+2)
    const float* Ag = A  + (size_t)(m0 + r) * K + ch * 4;
    const float* Bg = Bt + (size_t)(n0 + r) * K + ch * 4;
    const uint32_t sb = smem_u32(smf);
    const uint32_t srow = (uint32_t)(r * (LDP * 4)) + (uint32_t)(ch * 16);

    auto load = [&](int kt) {
        const int s = kt % 3;
        const uint32_t sa = sb + (uint32_t)(s * STAGEF * 4) + srow;
        const uint32_t sbb = sa + STGF * 4;
        const float* ag = Ag + kt * BK;
        const float* bg = Bg + kt * BK;
        CP16(sa,      ag);
        CP16(sa + 32, ag + 8);
        CP16(sbb,      bg);
        CP16(sbb + 32, bg + 8);
        CP_COMMIT();
    };

    load(0);
    load(1);

    float acc[4][4][4];
    #pragma unroll
    for (int i = 0; i < 4; ++i)
        #pragma unroll
        for (int j = 0; j < 4; ++j)
            #pragma unroll
            for (int q = 0; q < 4; ++q) acc[i][j][q] = 0.f;

    const int gm = lane >> 2;     // 0..7
    const int kq = lane & 3;      // 0..3

    for (int kt = 0; kt < NT; ++kt) {
        if (kt < NT - 1) asm volatile("cp.async.wait_group 1;" ::: "memory");
        else             asm volatile("cp.async.wait_group 0;" ::: "memory");
        __syncthreads();
        if (kt + 2 < NT) load(kt + 2);

        const float* As = smf + (size_t)(kt % 3) * STAGEF;
        const float* Bs = As + STGF;
        const uint32_t* Asu = reinterpret_cast<const uint32_t*>(As);
        const uint32_t* Bsu = reinterpret_cast<const uint32_t*>(Bs);

        #pragma unroll
        for (int ks = 0; ks < 2; ++ks) {
            const int kb = ks * 8 + kq;
            uint32_t af[4][4];
            #pragma unroll
            for (int mi = 0; mi < 4; ++mi) {
                const int ml = wm * 64 + mi * 16 + gm;
                af[mi][0] = Asu[ml * LDP + kb];
                af[mi][1] = Asu[(ml + 8) * LDP + kb];
                af[mi][2] = Asu[ml * LDP + kb + 4];
                af[mi][3] = Asu[(ml + 8) * LDP + kb + 4];
            }
            uint32_t bf[4][2];
            #pragma unroll
            for (int ni = 0; ni < 4; ++ni) {
                const int nl = wn * 32 + ni * 8 + gm;
                bf[ni][0] = Bsu[nl * LDP + kb];
                bf[ni][1] = Bsu[nl * LDP + kb + 4];
            }
            #pragma unroll
            for (int mi = 0; mi < 4; ++mi)
                #pragma unroll
                for (int ni = 0; ni < 4; ++ni) {
                    float* d = acc[mi][ni];
                    asm volatile(
                        "mma.sync.aligned.m16n8k8.row.col.f32.tf32.tf32.f32 "
                        "{%0,%1,%2,%3}, {%4,%5,%6,%7}, {%8,%9}, {%0,%1,%2,%3};"
                        : "+f"(d[0]), "+f"(d[1]), "+f"(d[2]), "+f"(d[3])
                        : "r"(af[mi][0]), "r"(af[mi][1]), "r"(af[mi][2]), "r"(af[mi][3]),
                          "r"(bf[ni][0]), "r"(bf[ni][1]));
                }
        }
    }

    // ---- epilogue: bias + store (float2 per half-tile row) ----
    const int colq = (lane & 3) * 2;
    #pragma unroll
    for (int ni = 0; ni < 4; ++ni) {
        const int col = n0 + wn * 32 + ni * 8 + colq;
        const float b0 = bias[col], b1 = bias[col + 1];
        #pragma unroll
        for (int mi = 0; mi < 4; ++mi) {
            const int row = m0 + wm * 64 + mi * 16 + gm;
            float2 v0 = {acc[mi][ni][0] + b0, acc[mi][ni][1] + b1};
            float2 v1 = {acc[mi][ni][2] + b0, acc[mi][ni][3] + b1};
            *reinterpret_cast<float2*>(C + (size_t)row * N + col) = v0;
            *reinterpret_cast<float2*>(C + (size_t)(row + 8) * N + col) = v1;
        }
    }
}

// ---------------- row LayerNorm (N = 512 or 1536) ---------------------------
__global__ void __launch_bounds__(256) ln_kernel(
    const float* __restrict__ X, const float* __restrict__ gamma,
    const float* __restrict__ beta, float* __restrict__ Y, int N)
{
    const int b = blockIdx.x;
    const float* x = X + (size_t)b * N;
    float* y       = Y + (size_t)b * N;
    const int cnt = N >> 8;                  // 2 or 6
    float v[6];
    float s = 0.f, ss = 0.f;
    for (int i = 0; i < cnt; ++i) {
        float t = x[threadIdx.x + (i << 8)];
        v[i] = t;
        s += t;
        ss = fmaf(t, t, ss);
    }
    __shared__ float sh[2][8];
    const int lane = threadIdx.x & 31, w = threadIdx.x >> 5;
    #pragma unroll
    for (int o = 16; o > 0; o >>= 1) {
        s  += __shfl_down_sync(0xffffffffu, s, o);
        ss += __shfl_down_sync(0xffffffffu, ss, o);
    }
    if (lane == 0) { sh[0][w] = s; sh[1][w] = ss; }
    __syncthreads();
    if (w == 0) {
        s  = (lane < 8) ? sh[0][lane] : 0.f;
        ss = (lane < 8) ? sh[1][lane] : 0.f;
        #pragma unroll
        for (int o = 4; o > 0; o >>= 1) {
            s  += __shfl_down_sync(0xffffffffu, s, o);
            ss += __shfl_down_sync(0xffffffffu, ss, o);
        }
        if (lane == 0) { sh[0][0] = s; sh[1][0] = ss; }
    }
    __syncthreads();
    const float invN = 1.0f / (float)N;
    const float mu   = sh[0][0] * invN;
    const float var  = sh[1][0] * invN - mu * mu;
    const float rr   = rsqrtf(var + EPSV);
    for (int i = 0; i < cnt; ++i) {
        int c = threadIdx.x + (i << 8);
        y[c] = (v[i] - mu) * rr * gamma[c] + beta[c];
    }
}

// ---------------- attention over tau + trend + fusion gate ------------------
__global__ void __launch_bounds__(128) attn_fusion(
    const float* __restrict__ T_t,   const float* __restrict__ t_att,
    const float* __restrict__ s_att, const float* __restrict__ s_next,
    const float* __restrict__ t_next, float* __restrict__ T_fusion)
{
    const int b = blockIdx.x;
    const int tid = threadIdx.x;
    const size_t off = (size_t)b * HDIM;

    float sn[4];
    #pragma unroll
    for (int i = 0; i < 4; ++i) sn[i] = s_next[off + tid + i * 128];

    float dot[NTAU];
    #pragma unroll
    for (int t = 0; t < NTAU; ++t) {
        const float* sa = s_att + ((size_t)t * BDIM + b) * HDIM;
        float d = 0.f;
        #pragma unroll
        for (int i = 0; i < 4; ++i) d = fmaf(sa[tid + i * 128], sn[i], d);
        dot[t] = d;
    }

    __shared__ float sh[NTAU][4];
    const int lane = tid & 31, w = tid >> 5;
    #pragma unroll
    for (int t = 0; t < NTAU; ++t) {
        float d = dot[t];
        #pragma unroll
        for (int o = 16; o > 0; o >>= 1) d += __shfl_down_sync(0xffffffffu, d, o);
        if (lane == 0) sh[t][w] = d;
    }
    __syncthreads();

    const float scale = rsqrtf((float)HDIM);
    float wt[NTAU], mx = -1e30f;
    #pragma unroll
    for (int t = 0; t < NTAU; ++t) {
        float v = (sh[t][0] + sh[t][1] + sh[t][2] + sh[t][3]) * scale;
        wt[t] = v;
        mx = fmaxf(mx, v);
    }
    float sum = 0.f;
    #pragma unroll
    for (int t = 0; t < NTAU; ++t) { wt[t] = expf(wt[t] - mx); sum += wt[t]; }
    const float inv = 1.0f / sum;

    #pragma unroll
    for (int i = 0; i < 4; ++i) {
        const int col = tid + i * 128;
        float trend = 0.f;
        #pragma unroll
        for (int t = 0; t < NTAU; ++t)
            trend = fmaf(wt[t], t_att[((size_t)t * BDIM + b) * HDIM + col], trend);
        trend *= inv;
        const float g = 1.0f / (1.0f + expf(-t_next[off + col]));
        T_fusion[off + col] = rna_tf32(T_t[off + col] * g + (1.0f - g) * trend);
    }
}

// ---------------- final split / gating / residual ---------------------------
__global__ void __launch_bounds__(256) final_gate(
    const float* __restrict__ Tcat, const float* __restrict__ Scat,
    const float* __restrict__ S_t,  float* __restrict__ out)
{
    const size_t i = (size_t)blockIdx.x * 256 + threadIdx.x;   // over B*H
    const int b = (int)(i >> 9);
    const int j = (int)(i & 511);
    const float* tr = Tcat + (size_t)b * 3 * HDIM;
    const float* sr = Scat + (size_t)b * 3 * HDIM;
    const float tg = 1.0f / (1.0f + expf(-tr[j]));
    const float sg = 1.0f / (1.0f + expf(-sr[j]));
    const float T_new = tg * tr[HDIM + j] + (1.0f - tg) * sr[HDIM + j];
    const float S_new = sg * sr[2 * HDIM + j] + (1.0f - sg) * tr[2 * HDIM + j] + S_t[i];
    out[i] = T_new;
    out[(size_t)BDIM * HDIM + i] = S_new;
}

// ---------------- launch -----------------------------------------------------
extern "C" void kernel_launch(void* const* d_in, const int* in_sizes, int n_in,
                              void* d_out, int out_size)
{
    const float* T_t   = (const float*)d_in[0];
    const float* S_t   = (const float*)d_in[1];
    const float* t_att = (const float*)d_in[2];
    const float* s_att = (const float*)d_in[3];
    const float* W_tn  = (const float*)d_in[4];
    const float* b_tn  = (const float*)d_in[5];
    const float* g_tn  = (const float*)d_in[6];
    const float* be_tn = (const float*)d_in[7];
    const float* W_sn  = (const float*)d_in[8];
    const float* b_sn  = (const float*)d_in[9];
    const float* g_sn  = (const float*)d_in[10];
    const float* be_sn = (const float*)d_in[11];
    const float* W_t   = (const float*)d_in[12];
    const float* b_t   = (const float*)d_in[13];
    const float* g_t   = (const float*)d_in[14];
    const float* be_t  = (const float*)d_in[15];
    const float* W_s   = (const float*)d_in[16];
    const float* b_s   = (const float*)d_in[17];
    const float* g_s   = (const float*)d_in[18];
    const float* be_s  = (const float*)d_in[19];
    float* out = (float*)d_out;

    float *bufT, *bufS, *snext, *tnext, *tfus, *Tr, *Sr;
    float *Wtn_t, *Wsn_t, *Wt_t, *Ws_t;
    cudaGetSymbolAddress((void**)&bufT,  g_bufT);
    cudaGetSymbolAddress((void**)&bufS,  g_bufS);
    cudaGetSymbolAddress((void**)&snext, g_snext);
    cudaGetSymbolAddress((void**)&tnext, g_tnext);
    cudaGetSymbolAddress((void**)&tfus,  g_tfus);
    cudaGetSymbolAddress((void**)&Tr,    g_Tr);
    cudaGetSymbolAddress((void**)&Sr,    g_Sr);
    cudaGetSymbolAddress((void**)&Wtn_t, g_Wtn_t);
    cudaGetSymbolAddress((void**)&Wsn_t, g_Wsn_t);
    cudaGetSymbolAddress((void**)&Wt_t,  g_Wt_t);
    cudaGetSymbolAddress((void**)&Ws_t,  g_Ws_t);

    const int GEMM_SMEM = 3 * 2 * 128 * 20 * 4;   // 61440 B
    cudaFuncSetAttribute(gemm_tf32, cudaFuncAttributeMaxDynamicSharedMemorySize,
                         GEMM_SMEM);

    // ---- pre-passes: transpose+round weights, round activations ----
    transpose_rna<<<dim3(HDIM / 32, HDIM / 32), dim3(32, 32)>>>(W_sn, Wsn_t, HDIM, HDIM);
    transpose_rna<<<dim3(HDIM / 32, HDIM / 32), dim3(32, 32)>>>(W_tn, Wtn_t, HDIM, HDIM);
    transpose_rna<<<dim3(3 * HDIM / 32, HDIM / 32), dim3(32, 32)>>>(W_t, Wt_t, HDIM, 3 * HDIM);
    transpose_rna<<<dim3(3 * HDIM / 32, HDIM / 32), dim3(32, 32)>>>(W_s, Ws_t, HDIM, 3 * HDIM);
    rna_copy<<<(BDIM * HDIM) / 1024, 256>>>(S_t, Sr);
    rna_copy<<<(BDIM * HDIM) / 1024, 256>>>(T_t, Tr);

    const dim3 gH(HDIM / 128, BDIM / 128);        // 4 x 128
    const dim3 g3H(3 * HDIM / 128, BDIM / 128);   // 12 x 128

    // s_next = LN(S_t @ W_sn + b_sn)
    gemm_tf32<<<gH, 256, GEMM_SMEM>>>(Sr, Wsn_t, b_sn, bufS, HDIM);
    ln_kernel<<<BDIM, 256>>>(bufS, g_sn, be_sn, snext, HDIM);
    // t_next = LN(T_t @ W_tn + b_tn)
    gemm_tf32<<<gH, 256, GEMM_SMEM>>>(Tr, Wtn_t, b_tn, bufT, HDIM);
    ln_kernel<<<BDIM, 256>>>(bufT, g_tn, be_tn, tnext, HDIM);
    // attention + fusion gate (writes tf32-rounded T_fusion)
    attn_fusion<<<BDIM, 128>>>(T_t, t_att, s_att, snext, tnext, tfus);
    // T_concat = LN(T_fusion @ W_t + b_t)
    gemm_tf32<<<g3H, 256, GEMM_SMEM>>>(tfus, Wt_t, b_t, bufT, 3 * HDIM);
    ln_kernel<<<BDIM, 256>>>(bufT, g_t, be_t, bufT, 3 * HDIM);
    // S_concat = LN(S_t @ W_s + b_s)
    gemm_tf32<<<g3H, 256, GEMM_SMEM>>>(Sr, Ws_t, b_s, bufS, 3 * HDIM);
    ln_kernel<<<BDIM, 256>>>(bufS, g_s, be_s, bufS, 3 * HDIM);
    // outputs
    final_gate<<<(BDIM * HDIM) / 256, 256>>>(bufT, bufS, S_t, out);
}

// round 4
// speedup vs baseline: 2.3411x; 1.1127x over previous
#include <cuda_runtime.h>
#include <math.h>
#include <stdint.h>

#define BDIM 16384
#define HDIM 512
#define NTAU 5
#define EPSV 1e-5f

// ---------------- scratch (static __device__: allocation-guard safe) --------
__device__ float g_bufT[(size_t)BDIM * 3 * HDIM];   // 96 MB
__device__ float g_bufS[(size_t)BDIM * 3 * HDIM];   // 96 MB
__device__ float g_snext[(size_t)BDIM * HDIM];
__device__ float g_tnext[(size_t)BDIM * HDIM];
__device__ float g_tfus[(size_t)BDIM * HDIM];       // tf32-rounded
__device__ float g_Tr[(size_t)BDIM * HDIM];         // tf32-rounded T_t
__device__ float g_Sr[(size_t)BDIM * HDIM];         // tf32-rounded S_t
__device__ float g_Wtn_t[(size_t)HDIM * HDIM];      // transposed+rounded weights
__device__ float g_Wsn_t[(size_t)HDIM * HDIM];
__device__ float g_Wt_t[(size_t)3 * HDIM * HDIM];
__device__ float g_Ws_t[(size_t)3 * HDIM * HDIM];

// ---------------- helpers ----------------------------------------------------
__device__ __forceinline__ uint32_t smem_u32(const void* p) {
    uint32_t a;
    asm("{ .reg .u64 t; cvta.to.shared.u64 t, %1; cvt.u32.u64 %0, t; }" : "=r"(a) : "l"(p));
    return a;
}
__device__ __forceinline__ float rna_tf32(float x) {
    uint32_t r;
    asm("cvt.rna.tf32.f32 %0, %1;" : "=r"(r) : "f"(x));
    return __uint_as_float(r);
}
__device__ __forceinline__ float sigmoidf_(float x) {
    return 1.0f / (1.0f + __expf(-x));
}
#define CP16(s, g) asm volatile("cp.async.cg.shared.global [%0], [%1], 16;" :: "r"(s), "l"(g))
#define CP_COMMIT() asm volatile("cp.async.commit_group;" ::: "memory")

// ---------------- weight transpose + RNA-tf32 round -------------------------
__global__ void transpose_rna(const float* __restrict__ W, float* __restrict__ Wt,
                              int K, int N)
{
    __shared__ float tile[32][33];
    const int x = blockIdx.x * 32 + threadIdx.x;   // n
    const int y = blockIdx.y * 32 + threadIdx.y;   // k
    tile[threadIdx.y][threadIdx.x] = W[(size_t)y * N + x];
    __syncthreads();
    const int xo = blockIdx.y * 32 + threadIdx.x;  // k
    const int yo = blockIdx.x * 32 + threadIdx.y;  // n
    Wt[(size_t)yo * K + xo] = rna_tf32(tile[threadIdx.x][threadIdx.y]);
}

// ---------------- RNA-tf32 rounding copy -------------------------------------
__global__ void __launch_bounds__(256) rna_copy(const float* __restrict__ in,
                                                float* __restrict__ out)
{
    const size_t i = ((size_t)blockIdx.x * 256 + threadIdx.x) * 4;
    float4 v = *reinterpret_cast<const float4*>(in + i);
    v.x = rna_tf32(v.x); v.y = rna_tf32(v.y);
    v.z = rna_tf32(v.z); v.w = rna_tf32(v.w);
    *reinterpret_cast<float4*>(out + i) = v;
}

// ---------------- tf32 mma.sync GEMM: C[M,N] = A[M,K] * Bt[N,K]^T + bias ----
// 128x128 CTA tile, BK=16, 3-stage cp.async, warp tile 64x32 (4x4 m16n8k8).
__global__ void __launch_bounds__(256, 2) gemm_tf32(
    const float* __restrict__ A, const float* __restrict__ Bt,
    const float* __restrict__ bias, float* __restrict__ C, int N)
{
    constexpr int K = 512, BK = 16, NT = K / BK;   // 32 k-iters
    constexpr int LDP = 20;                        // padded row stride (floats)
    constexpr int STGF = 128 * LDP;                // floats per operand tile (2560)
    constexpr int STAGEF = 2 * STGF;               // floats per stage (A+B)
    extern __shared__ float smf[];

    const int tid  = threadIdx.x;
    const int wid  = tid >> 5;
    const int lane = tid & 31;
    const int wm   = wid & 1;      // 2 m-groups of 64
    const int wn   = wid >> 1;     // 4 n-groups of 32
    const int m0 = blockIdx.y * 128;
    const int n0 = blockIdx.x * 128;

    const int r   = tid >> 1;          // 0..127
    const int ch  = tid & 1;           // chunk 0/1
    const float* Ag = A  + (size_t)(m0 + r) * K + ch * 4;
    const float* Bg = Bt + (size_t)(n0 + r) * K + ch * 4;
    const uint32_t sb = smem_u32(smf);
    const uint32_t srow = (uint32_t)(r * (LDP * 4)) + (uint32_t)(ch * 16);

    auto load = [&](int kt) {
        const int s = kt % 3;
        const uint32_t sa = sb + (uint32_t)(s * STAGEF * 4) + srow;
        const uint32_t sbb = sa + STGF * 4;
        const float* ag = Ag + kt * BK;
        const float* bg = Bg + kt * BK;
        CP16(sa,      ag);
        CP16(sa + 32, ag + 8);
        CP16(sbb,      bg);
        CP16(sbb + 32, bg + 8);
        CP_COMMIT();
    };

    load(0);
    load(1);

    float acc[4][4][4];
    #pragma unroll
    for (int i = 0; i < 4; ++i)
        #pragma unroll
        for (int j = 0; j < 4; ++j)
            #pragma unroll
            for (int q = 0; q < 4; ++q) acc[i][j][q] = 0.f;

    const int gm = lane >> 2;
    const int kq = lane & 3;

    for (int kt = 0; kt < NT; ++kt) {
        if (kt < NT - 1) asm volatile("cp.async.wait_group 1;" ::: "memory");
        else             asm volatile("cp.async.wait_group 0;" ::: "memory");
        __syncthreads();
        if (kt + 2 < NT) load(kt + 2);

        const float* As = smf + (size_t)(kt % 3) * STAGEF;
        const float* Bs = As + STGF;
        const uint32_t* Asu = reinterpret_cast<const uint32_t*>(As);
        const uint32_t* Bsu = reinterpret_cast<const uint32_t*>(Bs);

        #pragma unroll
        for (int ks = 0; ks < 2; ++ks) {
            const int kb = ks * 8 + kq;
            uint32_t af[4][4];
            #pragma unroll
            for (int mi = 0; mi < 4; ++mi) {
                const int ml = wm * 64 + mi * 16 + gm;
                af[mi][0] = Asu[ml * LDP + kb];
                af[mi][1] = Asu[(ml + 8) * LDP + kb];
                af[mi][2] = Asu[ml * LDP + kb + 4];
                af[mi][3] = Asu[(ml + 8) * LDP + kb + 4];
            }
            uint32_t bf[4][2];
            #pragma unroll
            for (int ni = 0; ni < 4; ++ni) {
                const int nl = wn * 32 + ni * 8 + gm;
                bf[ni][0] = Bsu[nl * LDP + kb];
                bf[ni][1] = Bsu[nl * LDP + kb + 4];
            }
            #pragma unroll
            for (int mi = 0; mi < 4; ++mi)
                #pragma unroll
                for (int ni = 0; ni < 4; ++ni) {
                    float* d = acc[mi][ni];
                    asm volatile(
                        "mma.sync.aligned.m16n8k8.row.col.f32.tf32.tf32.f32 "
                        "{%0,%1,%2,%3}, {%4,%5,%6,%7}, {%8,%9}, {%0,%1,%2,%3};"
                        : "+f"(d[0]), "+f"(d[1]), "+f"(d[2]), "+f"(d[3])
                        : "r"(af[mi][0]), "r"(af[mi][1]), "r"(af[mi][2]), "r"(af[mi][3]),
                          "r"(bf[ni][0]), "r"(bf[ni][1]));
                }
        }
    }

    const int colq = (lane & 3) * 2;
    #pragma unroll
    for (int ni = 0; ni < 4; ++ni) {
        const int col = n0 + wn * 32 + ni * 8 + colq;
        const float b0 = bias[col], b1 = bias[col + 1];
        #pragma unroll
        for (int mi = 0; mi < 4; ++mi) {
            const int row = m0 + wm * 64 + mi * 16 + gm;
            float2 v0 = {acc[mi][ni][0] + b0, acc[mi][ni][1] + b1};
            float2 v1 = {acc[mi][ni][2] + b0, acc[mi][ni][3] + b1};
            *reinterpret_cast<float2*>(C + (size_t)row * N + col) = v0;
            *reinterpret_cast<float2*>(C + (size_t)(row + 8) * N + col) = v1;
        }
    }
}

// ---------------- LN(512), 128 threads/row, float4 --------------------------
__global__ void __launch_bounds__(128) ln512_kernel(
    const float* __restrict__ X, const float* __restrict__ gamma,
    const float* __restrict__ beta, float* __restrict__ Y)
{
    const int b = blockIdx.x;
    const float4* x4 = reinterpret_cast<const float4*>(X + (size_t)b * HDIM);
    float4* y4       = reinterpret_cast<float4*>(Y + (size_t)b * HDIM);
    const int tid = threadIdx.x;

    float4 v = x4[tid];
    float s  = v.x + v.y + v.z + v.w;
    float ss = fmaf(v.x, v.x, fmaf(v.y, v.y, fmaf(v.z, v.z, v.w * v.w)));

    __shared__ float sh[2][4];
    const int lane = tid & 31, w = tid >> 5;
    #pragma unroll
    for (int o = 16; o > 0; o >>= 1) {
        s  += __shfl_down_sync(0xffffffffu, s, o);
        ss += __shfl_down_sync(0xffffffffu, ss, o);
    }
    if (lane == 0) { sh[0][w] = s; sh[1][w] = ss; }
    __syncthreads();
    const float sumS  = sh[0][0] + sh[0][1] + sh[0][2] + sh[0][3];
    const float sumSS = sh[1][0] + sh[1][1] + sh[1][2] + sh[1][3];
    const float mu  = sumS * (1.0f / HDIM);
    const float var = sumSS * (1.0f / HDIM) - mu * mu;
    const float r   = rsqrtf(var + EPSV);

    const float4 g = reinterpret_cast<const float4*>(gamma)[tid];
    const float4 be = reinterpret_cast<const float4*>(beta)[tid];
    float4 o;
    o.x = (v.x - mu) * r * g.x + be.x;
    o.y = (v.y - mu) * r * g.y + be.y;
    o.z = (v.z - mu) * r * g.z + be.z;
    o.w = (v.w - mu) * r * g.w + be.w;
    y4[tid] = o;
}

// ---------------- fused LN(1536)x2 + split/gate/residual --------------------
// 384 threads/row: each thread one float4 of T_concat-raw and S_concat-raw.
__global__ void __launch_bounds__(384) ln_gate_kernel(
    const float* __restrict__ Tcat, const float* __restrict__ Scat,
    const float* __restrict__ S_t,
    const float* __restrict__ g_t, const float* __restrict__ be_t,
    const float* __restrict__ g_s, const float* __restrict__ be_s,
    float* __restrict__ out)
{
    constexpr int N3 = 3 * HDIM;         // 1536
    const int b = blockIdx.x;
    const int tid = threadIdx.x;
    const float4* tr4 = reinterpret_cast<const float4*>(Tcat + (size_t)b * N3);
    const float4* sr4 = reinterpret_cast<const float4*>(Scat + (size_t)b * N3);

    __shared__ float shT[N3];
    __shared__ float shS[N3];
    __shared__ float red[4][12];

    float4 tv = tr4[tid];
    float4 sv = sr4[tid];

    float sT  = tv.x + tv.y + tv.z + tv.w;
    float ssT = fmaf(tv.x, tv.x, fmaf(tv.y, tv.y, fmaf(tv.z, tv.z, tv.w * tv.w)));
    float sS  = sv.x + sv.y + sv.z + sv.w;
    float ssS = fmaf(sv.x, sv.x, fmaf(sv.y, sv.y, fmaf(sv.z, sv.z, sv.w * sv.w)));

    const int lane = tid & 31, w = tid >> 5;   // 12 warps
    #pragma unroll
    for (int o = 16; o > 0; o >>= 1) {
        sT  += __shfl_down_sync(0xffffffffu, sT,  o);
        ssT += __shfl_down_sync(0xffffffffu, ssT, o);
        sS  += __shfl_down_sync(0xffffffffu, sS,  o);
        ssS += __shfl_down_sync(0xffffffffu, ssS, o);
    }
    if (lane == 0) { red[0][w] = sT; red[1][w] = ssT; red[2][w] = sS; red[3][w] = ssS; }
    __syncthreads();
    float tS = 0.f, tSS = 0.f, zS = 0.f, zSS = 0.f;
    #pragma unroll
    for (int i = 0; i < 12; ++i) {
        tS += red[0][i]; tSS += red[1][i];
        zS += red[2][i]; zSS += red[3][i];
    }
    const float invN = 1.0f / (float)N3;
    const float muT  = tS * invN;
    const float varT = tSS * invN - muT * muT;
    const float rT   = rsqrtf(varT + EPSV);
    const float muS  = zS * invN;
    const float varS = zSS * invN - muS * muS;
    const float rS   = rsqrtf(varS + EPSV);

    const float4 gt = reinterpret_cast<const float4*>(g_t)[tid];
    const float4 bt = reinterpret_cast<const float4*>(be_t)[tid];
    const float4 gs = reinterpret_cast<const float4*>(g_s)[tid];
    const float4 bs = reinterpret_cast<const float4*>(be_s)[tid];

    const int c = tid * 4;
    shT[c + 0] = (tv.x - muT) * rT * gt.x + bt.x;
    shT[c + 1] = (tv.y - muT) * rT * gt.y + bt.y;
    shT[c + 2] = (tv.z - muT) * rT * gt.z + bt.z;
    shT[c + 3] = (tv.w - muT) * rT * gt.w + bt.w;
    shS[c + 0] = (sv.x - muS) * rS * gs.x + bs.x;
    shS[c + 1] = (sv.y - muS) * rS * gs.y + bs.y;
    shS[c + 2] = (sv.z - muS) * rS * gs.z + bs.z;
    shS[c + 3] = (sv.w - muS) * rS * gs.w + bs.w;
    __syncthreads();

    // gate over 512 columns with 384 threads
    for (int j = tid; j < HDIM; j += 384) {
        const float tg = sigmoidf_(shT[j]);
        const float sg = sigmoidf_(shS[j]);
        const float T_new = tg * shT[HDIM + j] + (1.0f - tg) * shS[HDIM + j];
        const float S_new = sg * shS[2 * HDIM + j] + (1.0f - sg) * shT[2 * HDIM + j]
                          + S_t[(size_t)b * HDIM + j];
        out[(size_t)b * HDIM + j] = T_new;
        out[(size_t)BDIM * HDIM + (size_t)b * HDIM + j] = S_new;
    }
}

// ---------------- attention over tau + trend + fusion gate (float4) ---------
__global__ void __launch_bounds__(128) attn_fusion(
    const float* __restrict__ T_t,   const float* __restrict__ t_att,
    const float* __restrict__ s_att, const float* __restrict__ s_next,
    const float* __restrict__ t_next, float* __restrict__ T_fusion)
{
    const int b = blockIdx.x;
    const int tid = threadIdx.x;
    const size_t off4 = ((size_t)b * HDIM) >> 2;

    const float4 sn = reinterpret_cast<const float4*>(s_next)[off4 + tid];

    float dot[NTAU];
    #pragma unroll
    for (int t = 0; t < NTAU; ++t) {
        const float4 sa = reinterpret_cast<const float4*>(s_att)[((size_t)t * BDIM * HDIM >> 2) + off4 + tid];
        dot[t] = fmaf(sa.x, sn.x, fmaf(sa.y, sn.y, fmaf(sa.z, sn.z, sa.w * sn.w)));
    }

    __shared__ float sh[NTAU][4];
    const int lane = tid & 31, w = tid >> 5;
    #pragma unroll
    for (int t = 0; t < NTAU; ++t) {
        float d = dot[t];
        #pragma unroll
        for (int o = 16; o > 0; o >>= 1) d += __shfl_down_sync(0xffffffffu, d, o);
        if (lane == 0) sh[t][w] = d;
    }
    __syncthreads();

    const float scale = rsqrtf((float)HDIM);
    float wt[NTAU], mx = -1e30f;
    #pragma unroll
    for (int t = 0; t < NTAU; ++t) {
        float v = (sh[t][0] + sh[t][1] + sh[t][2] + sh[t][3]) * scale;
        wt[t] = v;
        mx = fmaxf(mx, v);
    }
    float sum = 0.f;
    #pragma unroll
    for (int t = 0; t < NTAU; ++t) { wt[t] = expf(wt[t] - mx); sum += wt[t]; }
    const float inv = 1.0f / sum;
    #pragma unroll
    for (int t = 0; t < NTAU; ++t) wt[t] *= inv;

    float4 trend = {0.f, 0.f, 0.f, 0.f};
    #pragma unroll
    for (int t = 0; t < NTAU; ++t) {
        const float4 ta = reinterpret_cast<const float4*>(t_att)[((size_t)t * BDIM * HDIM >> 2) + off4 + tid];
        trend.x = fmaf(wt[t], ta.x, trend.x);
        trend.y = fmaf(wt[t], ta.y, trend.y);
        trend.z = fmaf(wt[t], ta.z, trend.z);
        trend.w = fmaf(wt[t], ta.w, trend.w);
    }

    const float4 tn = reinterpret_cast<const float4*>(t_next)[off4 + tid];
    const float4 tt = reinterpret_cast<const float4*>(T_t)[off4 + tid];
    float4 o;
    {
        const float g0 = sigmoidf_(tn.x);
        const float g1 = sigmoidf_(tn.y);
        const float g2 = sigmoidf_(tn.z);
        const float g3 = sigmoidf_(tn.w);
        o.x = rna_tf32(tt.x * g0 + (1.0f - g0) * trend.x);
        o.y = rna_tf32(tt.y * g1 + (1.0f - g1) * trend.y);
        o.z = rna_tf32(tt.z * g2 + (1.0f - g2) * trend.z);
        o.w = rna_tf32(tt.w * g3 + (1.0f - g3) * trend.w);
    }
    reinterpret_cast<float4*>(T_fusion)[off4 + tid] = o;
}

// ---------------- launch -----------------------------------------------------
extern "C" void kernel_launch(void* const* d_in, const int* in_sizes, int n_in,
                              void* d_out, int out_size)
{
    const float* T_t   = (const float*)d_in[0];
    const float* S_t   = (const float*)d_in[1];
    const float* t_att = (const float*)d_in[2];
    const float* s_att = (const float*)d_in[3];
    const float* W_tn  = (const float*)d_in[4];
    const float* b_tn  = (const float*)d_in[5];
    const float* g_tn  = (const float*)d_in[6];
    const float* be_tn = (const float*)d_in[7];
    const float* W_sn  = (const float*)d_in[8];
    const float* b_sn  = (const float*)d_in[9];
    const float* g_sn  = (const float*)d_in[10];
    const float* be_sn = (const float*)d_in[11];
    const float* W_t   = (const float*)d_in[12];
    const float* b_t   = (const float*)d_in[13];
    const float* g_t   = (const float*)d_in[14];
    const float* be_t  = (const float*)d_in[15];
    const float* W_s   = (const float*)d_in[16];
    const float* b_s   = (const float*)d_in[17];
    const float* g_s   = (const float*)d_in[18];
    const float* be_s  = (const float*)d_in[19];
    float* out = (float*)d_out;

    float *bufT, *bufS, *snext, *tnext, *tfus, *Tr, *Sr;
    float *Wtn_t, *Wsn_t, *Wt_t, *Ws_t;
    cudaGetSymbolAddress((void**)&bufT,  g_bufT);
    cudaGetSymbolAddress((void**)&bufS,  g_bufS);
    cudaGetSymbolAddress((void**)&snext, g_snext);
    cudaGetSymbolAddress((void**)&tnext, g_tnext);
    cudaGetSymbolAddress((void**)&tfus,  g_tfus);
    cudaGetSymbolAddress((void**)&Tr,    g_Tr);
    cudaGetSymbolAddress((void**)&Sr,    g_Sr);
    cudaGetSymbolAddress((void**)&Wtn_t, g_Wtn_t);
    cudaGetSymbolAddress((void**)&Wsn_t, g_Wsn_t);
    cudaGetSymbolAddress((void**)&Wt_t,  g_Wt_t);
    cudaGetSymbolAddress((void**)&Ws_t,  g_Ws_t);

    const int GEMM_SMEM = 3 * 2 * 128 * 20 * 4;   // 61440 B
    cudaFuncSetAttribute(gemm_tf32, cudaFuncAttributeMaxDynamicSharedMemorySize,
                         GEMM_SMEM);

    // ---- pre-passes ----
    transpose_rna<<<dim3(HDIM / 32, HDIM / 32), dim3(32, 32)>>>(W_sn, Wsn_t, HDIM, HDIM);
    transpose_rna<<<dim3(HDIM / 32, HDIM / 32), dim3(32, 32)>>>(W_tn, Wtn_t, HDIM, HDIM);
    transpose_rna<<<dim3(3 * HDIM / 32, HDIM / 32), dim3(32, 32)>>>(W_t, Wt_t, HDIM, 3 * HDIM);
    transpose_rna<<<dim3(3 * HDIM / 32, HDIM / 32), dim3(32, 32)>>>(W_s, Ws_t, HDIM, 3 * HDIM);
    rna_copy<<<(BDIM * HDIM) / 1024, 256>>>(S_t, Sr);
    rna_copy<<<(BDIM * HDIM) / 1024, 256>>>(T_t, Tr);

    const dim3 gH(HDIM / 128, BDIM / 128);        // 4 x 128
    const dim3 g3H(3 * HDIM / 128, BDIM / 128);   // 12 x 128

    // s_next = LN(S_t @ W_sn + b_sn)
    gemm_tf32<<<gH, 256, GEMM_SMEM>>>(Sr, Wsn_t, b_sn, bufS, HDIM);
    ln512_kernel<<<BDIM, 128>>>(bufS, g_sn, be_sn, snext);
    // t_next = LN(T_t @ W_tn + b_tn)
    gemm_tf32<<<gH, 256, GEMM_SMEM>>>(Tr, Wtn_t, b_tn, bufT, HDIM);
    ln512_kernel<<<BDIM, 128>>>(bufT, g_tn, be_tn, tnext);
    // attention + fusion gate (writes tf32-rounded T_fusion)
    attn_fusion<<<BDIM, 128>>>(T_t, t_att, s_att, snext, tnext, tfus);
    // raw T_concat / S_concat
    gemm_tf32<<<g3H, 256, GEMM_SMEM>>>(tfus, Wt_t, b_t, bufT, 3 * HDIM);
    gemm_tf32<<<g3H, 256, GEMM_SMEM>>>(Sr, Ws_t, b_s, bufS, 3 * HDIM);
    // fused LN + LN + gate + residual -> out
    ln_gate_kernel<<<BDIM, 384>>>(bufT, bufS, S_t, g_t, be_t, g_s, be_s, out);
}

// round 5
// speedup vs baseline: 4.3035x; 1.8383x over previous
#include <cuda_runtime.h>
#include <cuda_fp16.h>
#include <math.h>
#include <stdint.h>

#define BDIM 16384
#define HDIM 512
#define NTAU 5
#define EPSV 1e-5f

// ---------------- scratch (static __device__: allocation-guard safe) --------
__device__ float  g_bufT[(size_t)BDIM * 3 * HDIM];   // 96 MB (raw T_concat)
__device__ float  g_bufS[(size_t)BDIM * 3 * HDIM];   // 96 MB (raw S_concat)
__device__ float  g_tmp[(size_t)BDIM * HDIM];        // raw s_next / t_next
__device__ float  g_snext[(size_t)BDIM * HDIM];
__device__ float  g_tnext[(size_t)BDIM * HDIM];
__device__ __half g_tfus[(size_t)BDIM * HDIM];       // fp16 T_fusion
__device__ __half g_Tr[(size_t)BDIM * HDIM];         // fp16 T_t
__device__ __half g_Sr[(size_t)BDIM * HDIM];         // fp16 S_t
__device__ __half g_Wtn_t[(size_t)HDIM * HDIM];      // transposed fp16 weights
__device__ __half g_Wsn_t[(size_t)HDIM * HDIM];
__device__ __half g_Wt_t[(size_t)3 * HDIM * HDIM];
__device__ __half g_Ws_t[(size_t)3 * HDIM * HDIM];

// ---------------- helpers ----------------------------------------------------
__device__ __forceinline__ uint32_t smem_u32(const void* p) {
    uint32_t a;
    asm("{ .reg .u64 t; cvta.to.shared.u64 t, %1; cvt.u32.u64 %0, t; }" : "=r"(a) : "l"(p));
    return a;
}
__device__ __forceinline__ float sigmoidf_(float x) {
    return 1.0f / (1.0f + __expf(-x));
}
#define CP16(s, g) asm volatile("cp.async.cg.shared.global [%0], [%1], 16;" :: "r"(s), "l"(g))
#define CP_COMMIT() asm volatile("cp.async.commit_group;" ::: "memory")
#define LDM_X4(r0, r1, r2, r3, ad) \
    asm volatile("ldmatrix.sync.aligned.m8n8.x4.shared.b16 {%0,%1,%2,%3}, [%4];" \
        : "=r"(r0), "=r"(r1), "=r"(r2), "=r"(r3) : "r"(ad))

// ---------------- weight transpose + fp16 round ------------------------------
__global__ void transpose_h(const float* __restrict__ W, __half* __restrict__ Wt,
                            int K, int N)
{
    __shared__ float tile[32][33];
    const int x = blockIdx.x * 32 + threadIdx.x;   // n
    const int y = blockIdx.y * 32 + threadIdx.y;   // k
    tile[threadIdx.y][threadIdx.x] = W[(size_t)y * N + x];
    __syncthreads();
    const int xo = blockIdx.y * 32 + threadIdx.x;  // k
    const int yo = blockIdx.x * 32 + threadIdx.y;  // n
    Wt[(size_t)yo * K + xo] = __float2half_rn(tile[threadIdx.x][threadIdx.y]);
}

// ---------------- fp32 -> fp16 convert (both S_t and T_t in one launch) -----
__global__ void __launch_bounds__(256) cvt_h(
    const float* __restrict__ S, const float* __restrict__ T,
    __half* __restrict__ Sh, __half* __restrict__ Th)
{
    const float* in = blockIdx.y ? T : S;
    __half* out     = blockIdx.y ? Th : Sh;
    const size_t i = ((size_t)blockIdx.x * 256 + threadIdx.x) * 4;
    float4 v = *reinterpret_cast<const float4*>(in + i);
    __half2* o2 = reinterpret_cast<__half2*>(out + i);
    o2[0] = __floats2half2_rn(v.x, v.y);
    o2[1] = __floats2half2_rn(v.z, v.w);
}

// ---------------- fp16 mma.sync GEMM: C[M,N] = A[M,K] * Bt[N,K]^T + bias ----
// 128x128 CTA tile, BK=32, 3-stage cp.async, warp tile 64x32 (m16n8k16),
// ldmatrix.x4 fragment loads, fp32 accumulate.
__global__ void __launch_bounds__(256, 2) gemm_f16(
    const __half* __restrict__ A, const __half* __restrict__ Bt,
    const float* __restrict__ bias, float* __restrict__ C, int N)
{
    constexpr int K = 512, BK = 32, NT = K / BK;   // 16 k-iters
    constexpr int LDB = 80;                        // bytes per row (32h + 8h pad)
    constexpr int TILEB = 128 * LDB;               // 10240 B per operand tile
    constexpr int STAGEB = 2 * TILEB;              // 20480 B per stage
    extern __shared__ char smem[];
    const uint32_t sb = smem_u32(smem);

    const int tid  = threadIdx.x;
    const int wid  = tid >> 5;
    const int lane = tid & 31;
    const int wm   = wid & 1;      // 2 m-groups of 64
    const int wn   = wid >> 1;     // 4 n-groups of 32
    const int m0 = blockIdx.y * 128;
    const int n0 = blockIdx.x * 128;

    // cp.async: 2 threads per row, 16 halves (32B) each per operand
    const int r  = tid >> 1;
    const int ch = tid & 1;
    const __half* Ag = A  + (size_t)(m0 + r) * K + ch * 16;
    const __half* Bg = Bt + (size_t)(n0 + r) * K + ch * 16;
    const uint32_t srow = (uint32_t)(r * LDB + ch * 32);

    auto load = [&](int kt) {
        const uint32_t sa = sb + (uint32_t)((kt % 3) * STAGEB) + srow;
        const uint32_t sbb = sa + TILEB;
        const __half* ag = Ag + kt * BK;
        const __half* bg = Bg + kt * BK;
        CP16(sa,      ag);
        CP16(sa + 16, ag + 8);
        CP16(sbb,      bg);
        CP16(sbb + 16, bg + 8);
        CP_COMMIT();
    };

    load(0);
    load(1);

    float acc[4][4][4];
    #pragma unroll
    for (int i = 0; i < 4; ++i)
        #pragma unroll
        for (int j = 0; j < 4; ++j)
            #pragma unroll
            for (int q = 0; q < 4; ++q) acc[i][j][q] = 0.f;

    const int r8 = lane & 7;
    const int g  = lane >> 3;         // ldmatrix lane group 0..3
    const int ga = g & 1;             // A: +8 rows
    const int gb = g >> 1;            // A: +8 k-halves

    for (int kt = 0; kt < NT; ++kt) {
        if (kt < NT - 1) asm volatile("cp.async.wait_group 1;" ::: "memory");
        else             asm volatile("cp.async.wait_group 0;" ::: "memory");
        __syncthreads();
        if (kt + 2 < NT) load(kt + 2);

        const uint32_t st = sb + (uint32_t)((kt % 3) * STAGEB);

        #pragma unroll
        for (int ks = 0; ks < 2; ++ks) {
            // A fragments: 4x ldmatrix.x4 (16x16 halves each)
            uint32_t af[4][4];
            #pragma unroll
            for (int mi = 0; mi < 4; ++mi) {
                const uint32_t ad = st +
                    (uint32_t)((wm * 64 + mi * 16 + ga * 8 + r8) * LDB +
                               (ks * 16 + gb * 8) * 2);
                LDM_X4(af[mi][0], af[mi][1], af[mi][2], af[mi][3], ad);
            }
            // B fragments: 2x ldmatrix.x4 (16 n-rows x 16 k-halves each)
            uint32_t bfr[2][4];
            #pragma unroll
            for (int p = 0; p < 2; ++p) {
                const uint32_t bd = st + TILEB +
                    (uint32_t)((wn * 32 + p * 16 + gb * 8 + r8) * LDB +
                               (ks * 16 + ga * 8) * 2);
                LDM_X4(bfr[p][0], bfr[p][1], bfr[p][2], bfr[p][3], bd);
            }
            #pragma unroll
            for (int mi = 0; mi < 4; ++mi)
                #pragma unroll
                for (int ni = 0; ni < 4; ++ni) {
                    float* d = acc[mi][ni];
                    const uint32_t b0 = bfr[ni >> 1][(ni & 1) * 2];
                    const uint32_t b1 = bfr[ni >> 1][(ni & 1) * 2 + 1];
                    asm volatile(
                        "mma.sync.aligned.m16n8k16.row.col.f32.f16.f16.f32 "
                        "{%0,%1,%2,%3}, {%4,%5,%6,%7}, {%8,%9}, {%0,%1,%2,%3};"
                        : "+f"(d[0]), "+f"(d[1]), "+f"(d[2]), "+f"(d[3])
                        : "r"(af[mi][0]), "r"(af[mi][1]), "r"(af[mi][2]), "r"(af[mi][3]),
                          "r"(b0), "r"(b1));
                }
        }
    }

    // ---- epilogue: bias + store ----
    const int gm   = lane >> 2;
    const int colq = (lane & 3) * 2;
    #pragma unroll
    for (int ni = 0; ni < 4; ++ni) {
        const int col = n0 + wn * 32 + ni * 8 + colq;
        const float b0 = bias[col], b1 = bias[col + 1];
        #pragma unroll
        for (int mi = 0; mi < 4; ++mi) {
            const int row = m0 + wm * 64 + mi * 16 + gm;
            float2 v0 = {acc[mi][ni][0] + b0, acc[mi][ni][1] + b1};
            float2 v1 = {acc[mi][ni][2] + b0, acc[mi][ni][3] + b1};
            *reinterpret_cast<float2*>(C + (size_t)row * N + col) = v0;
            *reinterpret_cast<float2*>(C + (size_t)(row + 8) * N + col) = v1;
        }
    }
}

// ---------------- LN(512), 128 threads/row, float4 --------------------------
__global__ void __launch_bounds__(128) ln512_kernel(
    const float* __restrict__ X, const float* __restrict__ gamma,
    const float* __restrict__ beta, float* __restrict__ Y)
{
    const int b = blockIdx.x;
    const float4* x4 = reinterpret_cast<const float4*>(X + (size_t)b * HDIM);
    float4* y4       = reinterpret_cast<float4*>(Y + (size_t)b * HDIM);
    const int tid = threadIdx.x;

    float4 v = x4[tid];
    float s  = v.x + v.y + v.z + v.w;
    float ss = fmaf(v.x, v.x, fmaf(v.y, v.y, fmaf(v.z, v.z, v.w * v.w)));

    __shared__ float sh[2][4];
    const int lane = tid & 31, w = tid >> 5;
    #pragma unroll
    for (int o = 16; o > 0; o >>= 1) {
        s  += __shfl_down_sync(0xffffffffu, s, o);
        ss += __shfl_down_sync(0xffffffffu, ss, o);
    }
    if (lane == 0) { sh[0][w] = s; sh[1][w] = ss; }
    __syncthreads();
    const float sumS  = sh[0][0] + sh[0][1] + sh[0][2] + sh[0][3];
    const float sumSS = sh[1][0] + sh[1][1] + sh[1][2] + sh[1][3];
    const float mu  = sumS * (1.0f / HDIM);
    const float var = sumSS * (1.0f / HDIM) - mu * mu;
    const float r   = rsqrtf(var + EPSV);

    const float4 gmm = reinterpret_cast<const float4*>(gamma)[tid];
    const float4 be = reinterpret_cast<const float4*>(beta)[tid];
    float4 o;
    o.x = (v.x - mu) * r * gmm.x + be.x;
    o.y = (v.y - mu) * r * gmm.y + be.y;
    o.z = (v.z - mu) * r * gmm.z + be.z;
    o.w = (v.w - mu) * r * gmm.w + be.w;
    y4[tid] = o;
}

// ---------------- fused LN(1536)x2 + split/gate/residual --------------------
__global__ void __launch_bounds__(384) ln_gate_kernel(
    const float* __restrict__ Tcat, const float* __restrict__ Scat,
    const float* __restrict__ S_t,
    const float* __restrict__ g_t, const float* __restrict__ be_t,
    const float* __restrict__ g_s, const float* __restrict__ be_s,
    float* __restrict__ out)
{
    constexpr int N3 = 3 * HDIM;         // 1536
    const int b = blockIdx.x;
    const int tid = threadIdx.x;
    const float4* tr4 = reinterpret_cast<const float4*>(Tcat + (size_t)b * N3);
    const float4* sr4 = reinterpret_cast<const float4*>(Scat + (size_t)b * N3);

    __shared__ float shT[N3];
    __shared__ float shS[N3];
    __shared__ float red[4][12];

    float4 tv = tr4[tid];
    float4 sv = sr4[tid];

    float sT  = tv.x + tv.y + tv.z + tv.w;
    float ssT = fmaf(tv.x, tv.x, fmaf(tv.y, tv.y, fmaf(tv.z, tv.z, tv.w * tv.w)));
    float sS  = sv.x + sv.y + sv.z + sv.w;
    float ssS = fmaf(sv.x, sv.x, fmaf(sv.y, sv.y, fmaf(sv.z, sv.z, sv.w * sv.w)));

    const int lane = tid & 31, w = tid >> 5;   // 12 warps
    #pragma unroll
    for (int o = 16; o > 0; o >>= 1) {
        sT  += __shfl_down_sync(0xffffffffu, sT,  o);
        ssT += __shfl_down_sync(0xffffffffu, ssT, o);
        sS  += __shfl_down_sync(0xffffffffu, sS,  o);
        ssS += __shfl_down_sync(0xffffffffu, ssS, o);
    }
    if (lane == 0) { red[0][w] = sT; red[1][w] = ssT; red[2][w] = sS; red[3][w] = ssS; }
    __syncthreads();
    float tS = 0.f, tSS = 0.f, zS = 0.f, zSS = 0.f;
    #pragma unroll
    for (int i = 0; i < 12; ++i) {
        tS += red[0][i]; tSS += red[1][i];
        zS += red[2][i]; zSS += red[3][i];
    }
    const float invN = 1.0f / (float)N3;
    const float muT  = tS * invN;
    const float varT = tSS * invN - muT * muT;
    const float rT   = rsqrtf(varT + EPSV);
    const float muS  = zS * invN;
    const float varS = zSS * invN - muS * muS;
    const float rS   = rsqrtf(varS + EPSV);

    const float4 gt = reinterpret_cast<const float4*>(g_t)[tid];
    const float4 bt = reinterpret_cast<const float4*>(be_t)[tid];
    const float4 gs = reinterpret_cast<const float4*>(g_s)[tid];
    const float4 bs = reinterpret_cast<const float4*>(be_s)[tid];

    const int c = tid * 4;
    shT[c + 0] = (tv.x - muT) * rT * gt.x + bt.x;
    shT[c + 1] = (tv.y - muT) * rT * gt.y + bt.y;
    shT[c + 2] = (tv.z - muT) * rT * gt.z + bt.z;
    shT[c + 3] = (tv.w - muT) * rT * gt.w + bt.w;
    shS[c + 0] = (sv.x - muS) * rS * gs.x + bs.x;
    shS[c + 1] = (sv.y - muS) * rS * gs.y + bs.y;
    shS[c + 2] = (sv.z - muS) * rS * gs.z + bs.z;
    shS[c + 3] = (sv.w - muS) * rS * gs.w + bs.w;
    __syncthreads();

    for (int j = tid; j < HDIM; j += 384) {
        const float tg = sigmoidf_(shT[j]);
        const float sg = sigmoidf_(shS[j]);
        const float T_new = tg * shT[HDIM + j] + (1.0f - tg) * shS[HDIM + j];
        const float S_new = sg * shS[2 * HDIM + j] + (1.0f - sg) * shT[2 * HDIM + j]
                          + S_t[(size_t)b * HDIM + j];
        out[(size_t)b * HDIM + j] = T_new;
        out[(size_t)BDIM * HDIM + (size_t)b * HDIM + j] = S_new;
    }
}

// ---------------- attention over tau + trend + fusion gate (float4) ---------
__global__ void __launch_bounds__(128) attn_fusion(
    const float* __restrict__ T_t,   const float* __restrict__ t_att,
    const float* __restrict__ s_att, const float* __restrict__ s_next,
    const float* __restrict__ t_next, __half* __restrict__ T_fusion)
{
    const int b = blockIdx.x;
    const int tid = threadIdx.x;
    const size_t off4 = ((size_t)b * HDIM) >> 2;

    const float4 sn = reinterpret_cast<const float4*>(s_next)[off4 + tid];

    float dot[NTAU];
    #pragma unroll
    for (int t = 0; t < NTAU; ++t) {
        const float4 sa = reinterpret_cast<const float4*>(s_att)[((size_t)t * BDIM * HDIM >> 2) + off4 + tid];
        dot[t] = fmaf(sa.x, sn.x, fmaf(sa.y, sn.y, fmaf(sa.z, sn.z, sa.w * sn.w)));
    }

    __shared__ float sh[NTAU][4];
    const int lane = tid & 31, w = tid >> 5;
    #pragma unroll
    for (int t = 0; t < NTAU; ++t) {
        float d = dot[t];
        #pragma unroll
        for (int o = 16; o > 0; o >>= 1) d += __shfl_down_sync(0xffffffffu, d, o);
        if (lane == 0) sh[t][w] = d;
    }
    __syncthreads();

    const float scale = rsqrtf((float)HDIM);
    float wt[NTAU], mx = -1e30f;
    #pragma unroll
    for (int t = 0; t < NTAU; ++t) {
        float v = (sh[t][0] + sh[t][1] + sh[t][2] + sh[t][3]) * scale;
        wt[t] = v;
        mx = fmaxf(mx, v);
    }
    float sum = 0.f;
    #pragma unroll
    for (int t = 0; t < NTAU; ++t) { wt[t] = expf(wt[t] - mx); sum += wt[t]; }
    const float inv = 1.0f / sum;
    #pragma unroll
    for (int t = 0; t < NTAU; ++t) wt[t] *= inv;

    float4 trend = {0.f, 0.f, 0.f, 0.f};
    #pragma unroll
    for (int t = 0; t < NTAU; ++t) {
        const float4 ta = reinterpret_cast<const float4*>(t_att)[((size_t)t * BDIM * HDIM >> 2) + off4 + tid];
        trend.x = fmaf(wt[t], ta.x, trend.x);
        trend.y = fmaf(wt[t], ta.y, trend.y);
        trend.z = fmaf(wt[t], ta.z, trend.z);
        trend.w = fmaf(wt[t], ta.w, trend.w);
    }

    const float4 tn = reinterpret_cast<const float4*>(t_next)[off4 + tid];
    const float4 tt = reinterpret_cast<const float4*>(T_t)[off4 + tid];
    const float g0 = sigmoidf_(tn.x);
    const float g1 = sigmoidf_(tn.y);
    const float g2 = sigmoidf_(tn.z);
    const float g3 = sigmoidf_(tn.w);
    const float o0 = tt.x * g0 + (1.0f - g0) * trend.x;
    const float o1 = tt.y * g1 + (1.0f - g1) * trend.y;
    const float o2 = tt.z * g2 + (1.0f - g2) * trend.z;
    const float o3 = tt.w * g3 + (1.0f - g3) * trend.w;
    __half2* out2 = reinterpret_cast<__half2*>(T_fusion) + off4 * 2 + tid * 2;
    out2[0] = __floats2half2_rn(o0, o1);
    out2[1] = __floats2half2_rn(o2, o3);
}

// ---------------- launch -----------------------------------------------------
extern "C" void kernel_launch(void* const* d_in, const int* in_sizes, int n_in,
                              void* d_out, int out_size)
{
    const float* T_t   = (const float*)d_in[0];
    const float* S_t   = (const float*)d_in[1];
    const float* t_att = (const float*)d_in[2];
    const float* s_att = (const float*)d_in[3];
    const float* W_tn  = (const float*)d_in[4];
    const float* b_tn  = (const float*)d_in[5];
    const float* g_tn  = (const float*)d_in[6];
    const float* be_tn = (const float*)d_in[7];
    const float* W_sn  = (const float*)d_in[8];
    const float* b_sn  = (const float*)d_in[9];
    const float* g_sn  = (const float*)d_in[10];
    const float* be_sn = (const float*)d_in[11];
    const float* W_t   = (const float*)d_in[12];
    const float* b_t   = (const float*)d_in[13];
    const float* g_t   = (const float*)d_in[14];
    const float* be_t  = (const float*)d_in[15];
    const float* W_s   = (const float*)d_in[16];
    const float* b_s   = (const float*)d_in[17];
    const float* g_s   = (const float*)d_in[18];
    const float* be_s  = (const float*)d_in[19];
    float* out = (float*)d_out;

    float *bufT, *bufS, *tmp, *snext, *tnext;
    __half *tfus, *Tr, *Sr, *Wtn_t, *Wsn_t, *Wt_t, *Ws_t;
    cudaGetSymbolAddress((void**)&bufT,  g_bufT);
    cudaGetSymbolAddress((void**)&bufS,  g_bufS);
    cudaGetSymbolAddress((void**)&tmp,   g_tmp);
    cudaGetSymbolAddress((void**)&snext, g_snext);
    cudaGetSymbolAddress((void**)&tnext, g_tnext);
    cudaGetSymbolAddress((void**)&tfus,  g_tfus);
    cudaGetSymbolAddress((void**)&Tr,    g_Tr);
    cudaGetSymbolAddress((void**)&Sr,    g_Sr);
    cudaGetSymbolAddress((void**)&Wtn_t, g_Wtn_t);
    cudaGetSymbolAddress((void**)&Wsn_t, g_Wsn_t);
    cudaGetSymbolAddress((void**)&Wt_t,  g_Wt_t);
    cudaGetSymbolAddress((void**)&Ws_t,  g_Ws_t);

    const int GEMM_SMEM = 3 * 20480;   // 61440 B
    cudaFuncSetAttribute(gemm_f16, cudaFuncAttributeMaxDynamicSharedMemorySize,
                         GEMM_SMEM);

    // ---- pre-passes (5 launches) ----
    transpose_h<<<dim3(HDIM / 32, HDIM / 32), dim3(32, 32)>>>(W_sn, Wsn_t, HDIM, HDIM);
    transpose_h<<<dim3(HDIM / 32, HDIM / 32), dim3(32, 32)>>>(W_tn, Wtn_t, HDIM, HDIM);
    transpose_h<<<dim3(3 * HDIM / 32, HDIM / 32), dim3(32, 32)>>>(W_t, Wt_t, HDIM, 3 * HDIM);
    transpose_h<<<dim3(3 * HDIM / 32, HDIM / 32), dim3(32, 32)>>>(W_s, Ws_t, HDIM, 3 * HDIM);
    cvt_h<<<dim3((BDIM * HDIM) / 1024, 2), 256>>>(S_t, T_t, Sr, Tr);

    const dim3 gH(HDIM / 128, BDIM / 128);        // 4 x 128
    const dim3 g3H(3 * HDIM / 128, BDIM / 128);   // 12 x 128

    // S_concat raw (first so ncu captures a GEMM)
    gemm_f16<<<g3H, 256, GEMM_SMEM>>>(Sr, Ws_t, b_s, bufS, 3 * HDIM);
    // s_next = LN(S_t @ W_sn + b_sn)
    gemm_f16<<<gH, 256, GEMM_SMEM>>>(Sr, Wsn_t, b_sn, tmp, HDIM);
    ln512_kernel<<<BDIM, 128>>>(tmp, g_sn, be_sn, snext);
    // t_next = LN(T_t @ W_tn + b_tn)
    gemm_f16<<<gH, 256, GEMM_SMEM>>>(Tr, Wtn_t, b_tn, tmp, HDIM);
    ln512_kernel<<<BDIM, 128>>>(tmp, g_tn, be_tn, tnext);
    // attention + fusion gate (writes fp16 T_fusion)
    attn_fusion<<<BDIM, 128>>>(T_t, t_att, s_att, snext, tnext, tfus);
    // T_concat raw
    gemm_f16<<<g3H, 256, GEMM_SMEM>>>(tfus, Wt_t, b_t, bufT, 3 * HDIM);
    // fused LN + LN + gate + residual -> out
    ln_gate_kernel<<<BDIM, 384>>>(bufT, bufS, S_t, g_t, be_t, g_s, be_s, out);
}